// round 1
// baseline (speedup 1.0000x reference)
#include <cuda_runtime.h>
#include <math.h>

#define N_CLUS 64
#define C_DIM 768
#define B_DIM 8
#define H_IN 32
#define HW 1024                 // 32*32
#define OUT_HW 512
#define NPIX (B_DIM * HW)       // 8192
#define RES_ELEMS ((size_t)B_DIM * N_CLUS * OUT_HW * OUT_HW)  // 134217728
#define CODE_ELEMS ((size_t)B_DIM * C_DIM * HW)               // 6291456
#define KC 32

__device__ float g_nclus[N_CLUS * C_DIM];
__device__ int   g_assign[NPIX];
__device__ float g_maxcos[NPIX];

// ---------------------------------------------------------------------------
// K1: L2-normalize cluster centroids. 64 blocks x 256 threads.
// ---------------------------------------------------------------------------
__global__ void norm_clusters_kernel(const float* __restrict__ clusters) {
    const int r = blockIdx.x;
    __shared__ float red[256];
    float s = 0.f;
    for (int i = threadIdx.x; i < C_DIM; i += 256) {
        float v = clusters[r * C_DIM + i];
        s = fmaf(v, v, s);
    }
    red[threadIdx.x] = s;
    __syncthreads();
    for (int o = 128; o > 0; o >>= 1) {
        if (threadIdx.x < o) red[threadIdx.x] += red[threadIdx.x + o];
        __syncthreads();
    }
    const float inv = 1.f / fmaxf(sqrtf(red[0]), 1e-12f);
    for (int i = threadIdx.x; i < C_DIM; i += 256)
        g_nclus[r * C_DIM + i] = clusters[r * C_DIM + i] * inv;
}

// ---------------------------------------------------------------------------
// K2: sims + per-pixel argmax + feature norm. 256 blocks x 128 threads.
// Block handles 32 pixels x all 64 clusters. Thread = 2 pixels x 8 clusters.
// ---------------------------------------------------------------------------
__global__ __launch_bounds__(128) void sim_kernel(const float* __restrict__ code) {
    const int tid = threadIdx.x;
    const int blk = blockIdx.x;          // 256 blocks
    const int b = blk >> 5;              // 32 blocks per batch image
    const int hwbase = (blk & 31) * 32;
    const int pid = tid & 15;            // pixel pair id (covers px 2*pid, 2*pid+1)
    const int ng = tid >> 4;             // cluster group (8 clusters each)
    const float* codeb = code + (size_t)b * C_DIM * HW + hwbase;

    __shared__ __align__(8) float codeS[KC][32];
    __shared__ float clusS[N_CLUS][KC];
    __shared__ float smv[8][32];
    __shared__ int   smn[8][32];
    __shared__ float snorm[32];

    float acc0[8], acc1[8];
#pragma unroll
    for (int j = 0; j < 8; ++j) { acc0[j] = 0.f; acc1[j] = 0.f; }
    float ssq0 = 0.f, ssq1 = 0.f;

    for (int c0 = 0; c0 < C_DIM; c0 += KC) {
        // stage code chunk: [KC][32 px], coalesced along px
#pragma unroll
        for (int k = 0; k < 8; ++k) {
            int idx = tid + k * 128;
            int c = idx >> 5, px = idx & 31;
            codeS[c][px] = codeb[(size_t)(c0 + c) * HW + px];
        }
        // stage normalized clusters chunk: [64][KC], coalesced along c
#pragma unroll
        for (int k = 0; k < 16; ++k) {
            int idx = tid + k * 128;
            int n = idx >> 5, c = idx & 31;
            clusS[n][c] = g_nclus[n * C_DIM + c0 + c];
        }
        __syncthreads();

        const float* crow = &clusS[ng * 8][0];
#pragma unroll 4
        for (int c = 0; c < KC; ++c) {
            float2 a = *(const float2*)&codeS[c][2 * pid];
            if (ng == 0) {  // fold feature sumsq into the same pass
                ssq0 = fmaf(a.x, a.x, ssq0);
                ssq1 = fmaf(a.y, a.y, ssq1);
            }
#pragma unroll
            for (int j = 0; j < 8; ++j) {
                float bv = crow[j * KC + c];
                acc0[j] = fmaf(a.x, bv, acc0[j]);
                acc1[j] = fmaf(a.y, bv, acc1[j]);
            }
        }
        __syncthreads();
    }

    // thread-local argmax over its 8 clusters (ascending n => first-max tiebreak)
    float mv0 = acc0[0], mv1 = acc1[0];
    int mn0 = ng * 8, mn1 = ng * 8;
#pragma unroll
    for (int j = 1; j < 8; ++j) {
        if (acc0[j] > mv0) { mv0 = acc0[j]; mn0 = ng * 8 + j; }
        if (acc1[j] > mv1) { mv1 = acc1[j]; mn1 = ng * 8 + j; }
    }
    smv[ng][2 * pid] = mv0;  smn[ng][2 * pid] = mn0;
    smv[ng][2 * pid + 1] = mv1;  smn[ng][2 * pid + 1] = mn1;
    if (ng == 0) { snorm[2 * pid] = ssq0; snorm[2 * pid + 1] = ssq1; }
    __syncthreads();

    if (tid < 32) {
        float best = smv[0][tid];
        int bn = smn[0][tid];
#pragma unroll
        for (int g = 1; g < 8; ++g) {  // ascending n groups => first-max tiebreak
            if (smv[g][tid] > best) { best = smv[g][tid]; bn = smn[g][tid]; }
        }
        const float nrm = fmaxf(sqrtf(snorm[tid]), 1e-12f);
        const int gp = blk * 32 + tid;
        g_assign[gp] = bn;
        g_maxcos[gp] = best / nrm;
    }
}

// ---------------------------------------------------------------------------
// K2b: deterministic loss reduction. 1 block x 256 threads.
// ---------------------------------------------------------------------------
__global__ void loss_kernel(float* __restrict__ out) {
    __shared__ float red[256];
    float s = 0.f;
    for (int i = threadIdx.x; i < NPIX; i += 256) s += g_maxcos[i];
    red[threadIdx.x] = s;
    __syncthreads();
    for (int o = 128; o > 0; o >>= 1) {
        if (threadIdx.x < o) red[threadIdx.x] += red[threadIdx.x + o];
        __syncthreads();
    }
    if (threadIdx.x == 0) out[0] = -red[0] / (float)NPIX;
}

// ---------------------------------------------------------------------------
// K3: bilinear-upsampled one-hot writer. Grid (4 xtiles, 512 y, 8 b) x 256.
// Each block owns a [64][128] output tile for one (b, y, x-tile):
//   zero smem -> scatter <=4 bilinear weights per x -> stream out coalesced.
// Output base is d_out+1 (4B misaligned) => scalar STG.32 only.
// ---------------------------------------------------------------------------
__global__ __launch_bounds__(256) void resize_kernel(float* __restrict__ out) {
    const int tid = threadIdx.x;
    const int xt = blockIdx.x, y = blockIdx.y, b = blockIdx.z;
    __shared__ __align__(16) float tile[N_CLUS][128];

#pragma unroll
    for (int k = 0; k < 8; ++k)
        ((float4*)&tile[0][0])[tid + k * 256] = make_float4(0.f, 0.f, 0.f, 0.f);
    __syncthreads();

    if (tid < 128) {
        const int x = xt * 128 + tid;
        const float fy = (y + 0.5f) * 0.0625f - 0.5f;
        const float fx = (x + 0.5f) * 0.0625f - 0.5f;
        const float y0f = floorf(fy), x0f = floorf(fx);
        const float wy1 = fy - y0f, wx1 = fx - x0f;
        const int y0 = (int)y0f, x0 = (int)x0f;
        const int ylo = max(y0, 0), yhi = min(y0 + 1, H_IN - 1);
        const int xlo = max(x0, 0), xhi = min(x0 + 1, H_IN - 1);
        const int bo = b * HW;
        const int a00 = g_assign[bo + ylo * H_IN + xlo];
        const int a01 = g_assign[bo + ylo * H_IN + xhi];
        const int a10 = g_assign[bo + yhi * H_IN + xlo];
        const int a11 = g_assign[bo + yhi * H_IN + xhi];
        const float wy0 = 1.f - wy1, wx0 = 1.f - wx1;
        // column `tid` is private to this thread; sequential RMW is safe and
        // handles duplicate cluster ids among the 4 neighbors correctly.
        tile[a00][tid] += wy0 * wx0;
        tile[a01][tid] += wy0 * wx1;
        tile[a10][tid] += wy1 * wx0;
        tile[a11][tid] += wy1 * wx1;
    }
    __syncthreads();

    // stream out: warp writes 128B contiguous per iteration
    float* ob = out + (size_t)b * (N_CLUS * OUT_HW * OUT_HW)
                    + (size_t)y * OUT_HW + (size_t)xt * 128;
#pragma unroll
    for (int k = 0; k < 32; ++k) {
        int idx = k * 256 + tid;
        int n = idx >> 7, i = idx & 127;
        ob[(size_t)n * (OUT_HW * OUT_HW) + i] = tile[n][i];
    }
}

// ---------------------------------------------------------------------------
// Launch: out layout = [loss(1)] [resized(134217728)] [code(6291456)]
// ---------------------------------------------------------------------------
extern "C" void kernel_launch(void* const* d_in, const int* in_sizes, int n_in,
                              void* d_out, int out_size) {
    const float* code = (const float*)d_in[0];
    const float* clusters = (const float*)d_in[1];
    float* out = (float*)d_out;

    norm_clusters_kernel<<<64, 256>>>(clusters);
    sim_kernel<<<256, 128>>>(code);
    loss_kernel<<<1, 256>>>(out);
    dim3 g3(4, 512, 8);
    resize_kernel<<<g3, 256>>>(out + 1);
    cudaMemcpyAsync(out + 1 + RES_ELEMS, code, CODE_ELEMS * sizeof(float),
                    cudaMemcpyDeviceToDevice, 0);
}